// round 1
// baseline (speedup 1.0000x reference)
#include <cuda_runtime.h>
#include <math.h>

#define HEADS 16
#define HD    64
#define SEQ   2048
#define BATCH 2
#define DIMM  1024
#define TDIM  3072
#define BT    (BATCH*SEQ)

// Scratch (no cudaMalloc allowed)
__device__ float g_qkv[(size_t)BT * TDIM];   // 50.3 MB: [b*T][3*D]
__device__ float g_att[(size_t)BT * DIMM];   // 16.8 MB: [b*T][D] (heads concatenated)

// ---------------------------------------------------------------------------
// C[M][N] = A[M][K] @ W[N][K]^T + bias[N]
// BM=BN=128, BK=8, 256 threads, 8x8 register tile per thread.
// ---------------------------------------------------------------------------
__global__ __launch_bounds__(256) void sgemm_bias(
    const float* __restrict__ A, const float* __restrict__ W,
    const float* __restrict__ bias, float* __restrict__ C,
    int N, int K)
{
    __shared__ float As[8][128];
    __shared__ float Ws[8][128];
    const int tid = threadIdx.x;
    const int m0 = blockIdx.y * 128;
    const int n0 = blockIdx.x * 128;
    const int ty = tid >> 4;       // 0..15
    const int tx = tid & 15;       // 0..15
    const int lr = tid >> 1;       // 0..127
    const int lc = (tid & 1) * 4;  // 0 or 4

    const float* Ag = A + (size_t)(m0 + lr) * K + lc;
    const float* Wg = W + (size_t)(n0 + lr) * K + lc;

    float acc[8][8];
#pragma unroll
    for (int i = 0; i < 8; i++)
#pragma unroll
        for (int j = 0; j < 8; j++) acc[i][j] = 0.f;

    for (int k0 = 0; k0 < K; k0 += 8) {
        float4 av = *(const float4*)(Ag + k0);
        float4 wv = *(const float4*)(Wg + k0);
        __syncthreads();
        As[lc + 0][lr] = av.x; As[lc + 1][lr] = av.y;
        As[lc + 2][lr] = av.z; As[lc + 3][lr] = av.w;
        Ws[lc + 0][lr] = wv.x; Ws[lc + 1][lr] = wv.y;
        Ws[lc + 2][lr] = wv.z; Ws[lc + 3][lr] = wv.w;
        __syncthreads();
#pragma unroll
        for (int k = 0; k < 8; k++) {
            float a[8], b[8];
            *(float4*)&a[0] = *(const float4*)&As[k][ty * 8];
            *(float4*)&a[4] = *(const float4*)&As[k][ty * 8 + 4];
            *(float4*)&b[0] = *(const float4*)&Ws[k][tx * 8];
            *(float4*)&b[4] = *(const float4*)&Ws[k][tx * 8 + 4];
#pragma unroll
            for (int i = 0; i < 8; i++)
#pragma unroll
                for (int j = 0; j < 8; j++)
                    acc[i][j] = fmaf(a[i], b[j], acc[i][j]);
        }
    }

#pragma unroll
    for (int i = 0; i < 8; i++) {
        const int m = m0 + ty * 8 + i;
#pragma unroll
        for (int j = 0; j < 8; j += 4) {
            const int n = n0 + tx * 8 + j;
            float4 v;
            v.x = acc[i][j + 0] + bias[n + 0];
            v.y = acc[i][j + 1] + bias[n + 1];
            v.z = acc[i][j + 2] + bias[n + 2];
            v.w = acc[i][j + 3] + bias[n + 3];
            *(float4*)&C[(size_t)m * N + n] = v;
        }
    }
}

// ---------------------------------------------------------------------------
// Flash attention, fp32. One block = (b, h, 64-query tile). 256 threads.
// S and O GEMMs use 4x4 register tiles on a 16x16 thread grid.
// ALiBi bias computed analytically; softmax in log2 domain (exp2f).
// ---------------------------------------------------------------------------
__global__ __launch_bounds__(256) void attn_kernel(const int* __restrict__ causal_p,
                                                   float* __restrict__ out)
{
    extern __shared__ float sm[];
    float* Qt = sm;               // [64 d][68] (d-major, m inner)
    float* Kt = Qt + 64 * 68;     // [64 d][68] (d-major, j inner)
    float* Vs = Kt + 64 * 68;     // [64 j][68] (j-major, d inner)
    float* Ps = Vs + 64 * 68;     // [64 m][68]

    const int qtile = blockIdx.x;
    const int bh    = blockIdx.y;
    const int b     = bh >> 4;
    const int h     = bh & 15;
    const int tid   = threadIdx.x;
    const int ty    = tid >> 4;   // 0..15
    const int tx    = tid & 15;   // 0..15
    const int causal = *causal_p;

    const float LOG2E  = 1.4426950408889634f;
    const float sscale = 0.125f * LOG2E;                       // 1/sqrt(64) * log2(e)
    const float slope2 = (float)(exp2(-0.5 * (double)(h + 1)) * 1.4426950408889634);

    const float* qkv = g_qkv;
    const int q0 = qtile * 64;

    // Load Q tile, transposed to [d][m]
    for (int i = tid; i < 1024; i += 256) {
        const int m = i >> 4;
        const int d = (i & 15) * 4;
        float4 v = *(const float4*)&qkv[(size_t)(b * SEQ + q0 + m) * TDIM + h * HD + d];
        Qt[(d + 0) * 68 + m] = v.x; Qt[(d + 1) * 68 + m] = v.y;
        Qt[(d + 2) * 68 + m] = v.z; Qt[(d + 3) * 68 + m] = v.w;
    }

    float m_i[4], l_i[4], o[4][4];
#pragma unroll
    for (int i = 0; i < 4; i++) {
        m_i[i] = -1e30f; l_i[i] = 0.f;
#pragma unroll
        for (int j = 0; j < 4; j++) o[i][j] = 0.f;
    }

    const int r0 = ty * 4, c0 = tx * 4;
    const int ntiles = causal ? (qtile + 1) : (SEQ / 64);

    for (int kt = 0; kt < ntiles; kt++) {
        __syncthreads();  // protect Vs/Kt (prev iter) and Qt (first iter)
        // Load K (transposed) and V tiles
        for (int i = tid; i < 1024; i += 256) {
            const int j = i >> 4;
            const int d = (i & 15) * 4;
            const size_t row = (size_t)(b * SEQ + kt * 64 + j) * TDIM + h * HD + d;
            float4 kv = *(const float4*)&qkv[row + DIMM];
            Kt[(d + 0) * 68 + j] = kv.x; Kt[(d + 1) * 68 + j] = kv.y;
            Kt[(d + 2) * 68 + j] = kv.z; Kt[(d + 3) * 68 + j] = kv.w;
            float4 vv = *(const float4*)&qkv[row + 2 * DIMM];
            *(float4*)&Vs[j * 68 + d] = vv;
        }
        __syncthreads();

        // S = Q K^T
        float s[4][4];
#pragma unroll
        for (int i = 0; i < 4; i++)
#pragma unroll
            for (int j = 0; j < 4; j++) s[i][j] = 0.f;

#pragma unroll 4
        for (int d = 0; d < 64; d++) {
            float4 aq = *(const float4*)&Qt[d * 68 + r0];
            float4 bk = *(const float4*)&Kt[d * 68 + c0];
            float a[4] = {aq.x, aq.y, aq.z, aq.w};
            float bb[4] = {bk.x, bk.y, bk.z, bk.w};
#pragma unroll
            for (int i = 0; i < 4; i++)
#pragma unroll
                for (int j = 0; j < 4; j++)
                    s[i][j] = fmaf(a[i], bb[j], s[i][j]);
        }

        // Online softmax (log2 domain)
#pragma unroll
        for (int i = 0; i < 4; i++) {
            const int qi = q0 + r0 + i;
            float sv[4];
            float mx = -1e30f;
#pragma unroll
            for (int j = 0; j < 4; j++) {
                const int kj = kt * 64 + c0 + j;
                float v = fmaf(s[i][j], sscale, slope2 * (float)(kj - qi));
                if (causal && kj > qi) v = -1e30f;
                sv[j] = v;
                mx = fmaxf(mx, v);
            }
#pragma unroll
            for (int msk = 8; msk >= 1; msk >>= 1)
                mx = fmaxf(mx, __shfl_xor_sync(0xffffffffu, mx, msk));
            const float mn = fmaxf(m_i[i], mx);
            const float rs = exp2f(m_i[i] - mn);
            float psum = 0.f;
#pragma unroll
            for (int j = 0; j < 4; j++) {
                const float p = exp2f(sv[j] - mn);
                Ps[(r0 + i) * 68 + c0 + j] = p;
                psum += p;
            }
#pragma unroll
            for (int msk = 8; msk >= 1; msk >>= 1)
                psum += __shfl_xor_sync(0xffffffffu, psum, msk);
            l_i[i] = l_i[i] * rs + psum;
            m_i[i] = mn;
#pragma unroll
            for (int j = 0; j < 4; j++) o[i][j] *= rs;
        }
        __syncthreads();

        // O += P V
#pragma unroll 4
        for (int j = 0; j < 64; j++) {
            float4 v4 = *(const float4*)&Vs[j * 68 + c0];
#pragma unroll
            for (int i = 0; i < 4; i++) {
                const float p = Ps[(r0 + i) * 68 + j];
                o[i][0] = fmaf(p, v4.x, o[i][0]);
                o[i][1] = fmaf(p, v4.y, o[i][1]);
                o[i][2] = fmaf(p, v4.z, o[i][2]);
                o[i][3] = fmaf(p, v4.w, o[i][3]);
            }
        }
    }

    // Normalize and write [b*T][h*HD + c]
#pragma unroll
    for (int i = 0; i < 4; i++) {
        const float inv = 1.f / l_i[i];
        const size_t row = (size_t)(b * SEQ + q0 + r0 + i) * DIMM + h * HD;
        float4 v;
        v.x = o[i][0] * inv; v.y = o[i][1] * inv;
        v.z = o[i][2] * inv; v.w = o[i][3] * inv;
        *(float4*)&out[row + c0] = v;
    }
}

extern "C" void kernel_launch(void* const* d_in, const int* in_sizes, int n_in,
                              void* d_out, int out_size)
{
    const float* x      = (const float*)d_in[0];
    const int*   causal = (const int*)d_in[1];
    // d_in[2] = alibi_bias: unused (computed analytically in-kernel)
    const float* Wqkv   = (const float*)d_in[3];
    const float* bqkv   = (const float*)d_in[4];
    const float* Wout   = (const float*)d_in[5];
    const float* bout   = (const float*)d_in[6];
    float* out = (float*)d_out;

    float *qkv, *att;
    cudaGetSymbolAddress((void**)&qkv, g_qkv);
    cudaGetSymbolAddress((void**)&att, g_att);

    const int attn_smem = 4 * 64 * 68 * 4;  // 69632 B
    cudaFuncSetAttribute(attn_kernel, cudaFuncAttributeMaxDynamicSharedMemorySize, attn_smem);

    dim3 g1(TDIM / 128, BT / 128);
    sgemm_bias<<<g1, 256>>>(x, Wqkv, bqkv, qkv, TDIM, DIMM);

    dim3 g2(SEQ / 64, BATCH * HEADS);
    attn_kernel<<<g2, 256, attn_smem>>>(causal, att);

    dim3 g3(DIMM / 128, BT / 128);
    sgemm_bias<<<g3, 256>>>(att, Wout, bout, out, DIMM, DIMM);
}

// round 3
// speedup vs baseline: 1.5792x; 1.5792x over previous
#include <cuda_runtime.h>
#include <math.h>
#include <stdint.h>

#define HEADS 16
#define HD    64
#define SEQ   2048
#define BATCH 2
#define DIMM  1024
#define TDIM  3072
#define BT    (BATCH*SEQ)

// Scratch (no cudaMalloc allowed)
__device__ float g_qkv[(size_t)BT * TDIM];   // 50.3 MB: [b*T][3*D]
__device__ float g_att[(size_t)BT * DIMM];   // 16.8 MB: [b*T][D]

__device__ __forceinline__ float to_tf32(float x) {
    uint32_t u;
    asm("cvt.rna.tf32.f32 %0, %1;" : "=r"(u) : "f"(x));
    return __uint_as_float(u);
}

// ---------------------------------------------------------------------------
// C[M][N] = A[M][K] @ W[N][K]^T + bias[N]   via mma.sync tf32 (m16n8k8)
// BM=BN=128, BK=16, 256 threads (8 warps), warp tile 32x64.
// Smem stride 20 floats -> conflict-free fragment loads for both A and B.
// ---------------------------------------------------------------------------
__global__ __launch_bounds__(256) void tgemm_bias(
    const float* __restrict__ A, const float* __restrict__ W,
    const float* __restrict__ bias, float* __restrict__ C,
    int N, int K)
{
    __shared__ float As[2][128][20];
    __shared__ float Ws[2][128][20];

    const int tid  = threadIdx.x;
    const int warp = tid >> 5;
    const int lane = tid & 31;
    const int g    = lane >> 2;   // groupID 0..7
    const int t    = lane & 3;    // thread-in-group 0..3

    const int m0 = blockIdx.y * 128;
    const int n0 = blockIdx.x * 128;
    const int wm = (warp >> 1) * 32;   // warp m offset 0/32/64/96
    const int wn = (warp & 1) * 64;    // warp n offset 0/64

    // Global load mapping: 128 rows x 16 cols per tile, 2 rows per thread
    const int lrow = tid >> 2;        // 0..63
    const int lcol = (tid & 3) * 4;   // 0,4,8,12

    const float* Ag = A + (size_t)(m0 + lrow) * K + lcol;
    const float* Wg = W + (size_t)(n0 + lrow) * K + lcol;
    const size_t rstep = (size_t)64 * K;

    float acc[2][8][4];
#pragma unroll
    for (int mi = 0; mi < 2; mi++)
#pragma unroll
        for (int ni = 0; ni < 8; ni++)
#pragma unroll
            for (int r = 0; r < 4; r++) acc[mi][ni][r] = 0.f;

    // Preload chunk 0 into smem buffer 0
    {
        float4 a0 = *(const float4*)(Ag);
        float4 a1 = *(const float4*)(Ag + rstep);
        float4 w0 = *(const float4*)(Wg);
        float4 w1 = *(const float4*)(Wg + rstep);
        As[0][lrow     ][lcol+0]=to_tf32(a0.x); As[0][lrow     ][lcol+1]=to_tf32(a0.y);
        As[0][lrow     ][lcol+2]=to_tf32(a0.z); As[0][lrow     ][lcol+3]=to_tf32(a0.w);
        As[0][lrow + 64][lcol+0]=to_tf32(a1.x); As[0][lrow + 64][lcol+1]=to_tf32(a1.y);
        As[0][lrow + 64][lcol+2]=to_tf32(a1.z); As[0][lrow + 64][lcol+3]=to_tf32(a1.w);
        Ws[0][lrow     ][lcol+0]=to_tf32(w0.x); Ws[0][lrow     ][lcol+1]=to_tf32(w0.y);
        Ws[0][lrow     ][lcol+2]=to_tf32(w0.z); Ws[0][lrow     ][lcol+3]=to_tf32(w0.w);
        Ws[0][lrow + 64][lcol+0]=to_tf32(w1.x); Ws[0][lrow + 64][lcol+1]=to_tf32(w1.y);
        Ws[0][lrow + 64][lcol+2]=to_tf32(w1.z); Ws[0][lrow + 64][lcol+3]=to_tf32(w1.w);
    }
    __syncthreads();

    int buf = 0;
    for (int k0 = 0; k0 < K; k0 += 16) {
        // Prefetch next chunk to registers
        float4 a0, a1, w0, w1;
        const bool has_next = (k0 + 16) < K;
        if (has_next) {
            a0 = *(const float4*)(Ag + k0 + 16);
            a1 = *(const float4*)(Ag + rstep + k0 + 16);
            w0 = *(const float4*)(Wg + k0 + 16);
            w1 = *(const float4*)(Wg + rstep + k0 + 16);
        }

        // Compute on current buffer: 2 k-steps of 8
#pragma unroll
        for (int ks = 0; ks < 16; ks += 8) {
            uint32_t af[2][4], bf[8][2];
#pragma unroll
            for (int mi = 0; mi < 2; mi++) {
                const int r = wm + mi * 16;
                af[mi][0] = __float_as_uint(As[buf][r + g    ][ks + t    ]);
                af[mi][1] = __float_as_uint(As[buf][r + g + 8][ks + t    ]);
                af[mi][2] = __float_as_uint(As[buf][r + g    ][ks + t + 4]);
                af[mi][3] = __float_as_uint(As[buf][r + g + 8][ks + t + 4]);
            }
#pragma unroll
            for (int ni = 0; ni < 8; ni++) {
                const int c = wn + ni * 8;
                bf[ni][0] = __float_as_uint(Ws[buf][c + g][ks + t    ]);
                bf[ni][1] = __float_as_uint(Ws[buf][c + g][ks + t + 4]);
            }
#pragma unroll
            for (int mi = 0; mi < 2; mi++)
#pragma unroll
                for (int ni = 0; ni < 8; ni++) {
                    asm volatile(
                        "mma.sync.aligned.m16n8k8.row.col.f32.tf32.tf32.f32 "
                        "{%0,%1,%2,%3}, {%4,%5,%6,%7}, {%8,%9}, {%0,%1,%2,%3};\n"
                        : "+f"(acc[mi][ni][0]), "+f"(acc[mi][ni][1]),
                          "+f"(acc[mi][ni][2]), "+f"(acc[mi][ni][3])
                        : "r"(af[mi][0]), "r"(af[mi][1]), "r"(af[mi][2]), "r"(af[mi][3]),
                          "r"(bf[ni][0]), "r"(bf[ni][1]));
                }
        }

        if (has_next) {
            const int nb = buf ^ 1;
            As[nb][lrow     ][lcol+0]=to_tf32(a0.x); As[nb][lrow     ][lcol+1]=to_tf32(a0.y);
            As[nb][lrow     ][lcol+2]=to_tf32(a0.z); As[nb][lrow     ][lcol+3]=to_tf32(a0.w);
            As[nb][lrow + 64][lcol+0]=to_tf32(a1.x); As[nb][lrow + 64][lcol+1]=to_tf32(a1.y);
            As[nb][lrow + 64][lcol+2]=to_tf32(a1.z); As[nb][lrow + 64][lcol+3]=to_tf32(a1.w);
            Ws[nb][lrow     ][lcol+0]=to_tf32(w0.x); Ws[nb][lrow     ][lcol+1]=to_tf32(w0.y);
            Ws[nb][lrow     ][lcol+2]=to_tf32(w0.z); Ws[nb][lrow     ][lcol+3]=to_tf32(w0.w);
            Ws[nb][lrow + 64][lcol+0]=to_tf32(w1.x); Ws[nb][lrow + 64][lcol+1]=to_tf32(w1.y);
            Ws[nb][lrow + 64][lcol+2]=to_tf32(w1.z); Ws[nb][lrow + 64][lcol+3]=to_tf32(w1.w);
        }
        __syncthreads();
        buf ^= 1;
    }

    // Epilogue: acc rows wm+mi*16+{g, g+8}, cols wn+ni*8+{2t, 2t+1}
#pragma unroll
    for (int mi = 0; mi < 2; mi++) {
#pragma unroll
        for (int ni = 0; ni < 8; ni++) {
            const int n = n0 + wn + ni * 8 + 2 * t;
            const float b0 = bias[n], b1 = bias[n + 1];
            const int mA = m0 + wm + mi * 16 + g;
            float2 v0; v0.x = acc[mi][ni][0] + b0; v0.y = acc[mi][ni][1] + b1;
            *(float2*)&C[(size_t)mA * N + n] = v0;
            float2 v1; v1.x = acc[mi][ni][2] + b0; v1.y = acc[mi][ni][3] + b1;
            *(float2*)&C[(size_t)(mA + 8) * N + n] = v1;
        }
    }
}

// ---------------------------------------------------------------------------
// Flash attention, fp32 (unchanged from round 1).
// ---------------------------------------------------------------------------
__global__ __launch_bounds__(256) void attn_kernel(const int* __restrict__ causal_p,
                                                   float* __restrict__ out)
{
    extern __shared__ float sm[];
    float* Qt = sm;               // [64 d][68]
    float* Kt = Qt + 64 * 68;     // [64 d][68]
    float* Vs = Kt + 64 * 68;     // [64 j][68]
    float* Ps = Vs + 64 * 68;     // [64 m][68]

    const int qtile = blockIdx.x;
    const int bh    = blockIdx.y;
    const int b     = bh >> 4;
    const int h     = bh & 15;
    const int tid   = threadIdx.x;
    const int ty    = tid >> 4;
    const int tx    = tid & 15;
    const int causal = *causal_p;

    const float sscale = 0.125f * 1.4426950408889634f;
    const float slope2 = (float)(exp2(-0.5 * (double)(h + 1)) * 1.4426950408889634);

    const float* qkv = g_qkv;
    const int q0 = qtile * 64;

    for (int i = tid; i < 1024; i += 256) {
        const int m = i >> 4;
        const int d = (i & 15) * 4;
        float4 v = *(const float4*)&qkv[(size_t)(b * SEQ + q0 + m) * TDIM + h * HD + d];
        Qt[(d + 0) * 68 + m] = v.x; Qt[(d + 1) * 68 + m] = v.y;
        Qt[(d + 2) * 68 + m] = v.z; Qt[(d + 3) * 68 + m] = v.w;
    }

    float m_i[4], l_i[4], o[4][4];
#pragma unroll
    for (int i = 0; i < 4; i++) {
        m_i[i] = -1e30f; l_i[i] = 0.f;
#pragma unroll
        for (int j = 0; j < 4; j++) o[i][j] = 0.f;
    }

    const int r0 = ty * 4, c0 = tx * 4;
    const int ntiles = causal ? (qtile + 1) : (SEQ / 64);

    for (int kt = 0; kt < ntiles; kt++) {
        __syncthreads();
        for (int i = tid; i < 1024; i += 256) {
            const int j = i >> 4;
            const int d = (i & 15) * 4;
            const size_t row = (size_t)(b * SEQ + kt * 64 + j) * TDIM + h * HD + d;
            float4 kv = *(const float4*)&qkv[row + DIMM];
            Kt[(d + 0) * 68 + j] = kv.x; Kt[(d + 1) * 68 + j] = kv.y;
            Kt[(d + 2) * 68 + j] = kv.z; Kt[(d + 3) * 68 + j] = kv.w;
            float4 vv = *(const float4*)&qkv[row + 2 * DIMM];
            *(float4*)&Vs[j * 68 + d] = vv;
        }
        __syncthreads();

        float s[4][4];
#pragma unroll
        for (int i = 0; i < 4; i++)
#pragma unroll
            for (int j = 0; j < 4; j++) s[i][j] = 0.f;

#pragma unroll 4
        for (int d = 0; d < 64; d++) {
            float4 aq = *(const float4*)&Qt[d * 68 + r0];
            float4 bk = *(const float4*)&Kt[d * 68 + c0];
            float a[4] = {aq.x, aq.y, aq.z, aq.w};
            float bb[4] = {bk.x, bk.y, bk.z, bk.w};
#pragma unroll
            for (int i = 0; i < 4; i++)
#pragma unroll
                for (int j = 0; j < 4; j++)
                    s[i][j] = fmaf(a[i], bb[j], s[i][j]);
        }

#pragma unroll
        for (int i = 0; i < 4; i++) {
            const int qi = q0 + r0 + i;
            float sv[4];
            float mx = -1e30f;
#pragma unroll
            for (int j = 0; j < 4; j++) {
                const int kj = kt * 64 + c0 + j;
                float v = fmaf(s[i][j], sscale, slope2 * (float)(kj - qi));
                if (causal && kj > qi) v = -1e30f;
                sv[j] = v;
                mx = fmaxf(mx, v);
            }
#pragma unroll
            for (int msk = 8; msk >= 1; msk >>= 1)
                mx = fmaxf(mx, __shfl_xor_sync(0xffffffffu, mx, msk));
            const float mn = fmaxf(m_i[i], mx);
            const float rs = exp2f(m_i[i] - mn);
            float psum = 0.f;
#pragma unroll
            for (int j = 0; j < 4; j++) {
                const float p = exp2f(sv[j] - mn);
                Ps[(r0 + i) * 68 + c0 + j] = p;
                psum += p;
            }
#pragma unroll
            for (int msk = 8; msk >= 1; msk >>= 1)
                psum += __shfl_xor_sync(0xffffffffu, psum, msk);
            l_i[i] = l_i[i] * rs + psum;
            m_i[i] = mn;
#pragma unroll
            for (int j = 0; j < 4; j++) o[i][j] *= rs;
        }
        __syncthreads();

#pragma unroll 4
        for (int j = 0; j < 64; j++) {
            float4 v4 = *(const float4*)&Vs[j * 68 + c0];
#pragma unroll
            for (int i = 0; i < 4; i++) {
                const float p = Ps[(r0 + i) * 68 + j];
                o[i][0] = fmaf(p, v4.x, o[i][0]);
                o[i][1] = fmaf(p, v4.y, o[i][1]);
                o[i][2] = fmaf(p, v4.z, o[i][2]);
                o[i][3] = fmaf(p, v4.w, o[i][3]);
            }
        }
    }

#pragma unroll
    for (int i = 0; i < 4; i++) {
        const float inv = 1.f / l_i[i];
        const size_t row = (size_t)(b * SEQ + q0 + r0 + i) * DIMM + h * HD;
        float4 v;
        v.x = o[i][0] * inv; v.y = o[i][1] * inv;
        v.z = o[i][2] * inv; v.w = o[i][3] * inv;
        *(float4*)&out[row + c0] = v;
    }
}

extern "C" void kernel_launch(void* const* d_in, const int* in_sizes, int n_in,
                              void* d_out, int out_size)
{
    const float* x      = (const float*)d_in[0];
    const int*   causal = (const int*)d_in[1];
    // d_in[2] = alibi_bias: unused (computed analytically in-kernel)
    const float* Wqkv   = (const float*)d_in[3];
    const float* bqkv   = (const float*)d_in[4];
    const float* Wout   = (const float*)d_in[5];
    const float* bout   = (const float*)d_in[6];
    float* out = (float*)d_out;

    float *qkv, *att;
    cudaGetSymbolAddress((void**)&qkv, g_qkv);
    cudaGetSymbolAddress((void**)&att, g_att);

    static bool attr_set = false;
    const int attn_smem = 4 * 64 * 68 * 4;  // 69632 B
    if (!attr_set) {
        cudaFuncSetAttribute(attn_kernel, cudaFuncAttributeMaxDynamicSharedMemorySize, attn_smem);
        attr_set = true;
    }

    dim3 g1(TDIM / 128, BT / 128);
    tgemm_bias<<<g1, 256>>>(x, Wqkv, bqkv, qkv, TDIM, DIMM);

    dim3 g2(SEQ / 64, BATCH * HEADS);
    attn_kernel<<<g2, 256, attn_smem>>>(causal, att);

    dim3 g3(DIMM / 128, BT / 128);
    tgemm_bias<<<g3, 256>>>(att, Wout, bout, out, DIMM, DIMM);
}

// round 4
// speedup vs baseline: 2.8374x; 1.7967x over previous
#include <cuda_runtime.h>
#include <math.h>
#include <stdint.h>

#define HEADS 16
#define HD    64
#define SEQ   2048
#define BATCH 2
#define DIMM  1024
#define TDIM  3072
#define BT    (BATCH*SEQ)

// Scratch (no cudaMalloc allowed)
__device__ float g_qkv[(size_t)BT * TDIM];   // [b*T][3*D]
__device__ float g_att[(size_t)BT * DIMM];   // [b*T][D]

__device__ __forceinline__ float to_tf32(float x) {
    uint32_t u;
    asm("cvt.rna.tf32.f32 %0, %1;" : "=r"(u) : "f"(x));
    return __uint_as_float(u);
}

__device__ __forceinline__ void mma_tf32(float* c, const uint32_t* a, const uint32_t* b) {
    asm volatile(
        "mma.sync.aligned.m16n8k8.row.col.f32.tf32.tf32.f32 "
        "{%0,%1,%2,%3}, {%4,%5,%6,%7}, {%8,%9}, {%0,%1,%2,%3};\n"
        : "+f"(c[0]), "+f"(c[1]), "+f"(c[2]), "+f"(c[3])
        : "r"(a[0]), "r"(a[1]), "r"(a[2]), "r"(a[3]), "r"(b[0]), "r"(b[1]));
}

// ---------------------------------------------------------------------------
// C[M][N] = A[M][K] @ W[N][K]^T + bias[N]   via mma.sync tf32 (m16n8k8)
// ---------------------------------------------------------------------------
__global__ __launch_bounds__(256) void tgemm_bias(
    const float* __restrict__ A, const float* __restrict__ W,
    const float* __restrict__ bias, float* __restrict__ C,
    int N, int K)
{
    __shared__ float As[2][128][20];
    __shared__ float Ws[2][128][20];

    const int tid  = threadIdx.x;
    const int warp = tid >> 5;
    const int lane = tid & 31;
    const int g    = lane >> 2;
    const int t    = lane & 3;

    const int m0 = blockIdx.y * 128;
    const int n0 = blockIdx.x * 128;
    const int wm = (warp >> 1) * 32;
    const int wn = (warp & 1) * 64;

    const int lrow = tid >> 2;
    const int lcol = (tid & 3) * 4;

    const float* Ag = A + (size_t)(m0 + lrow) * K + lcol;
    const float* Wg = W + (size_t)(n0 + lrow) * K + lcol;
    const size_t rstep = (size_t)64 * K;

    float acc[2][8][4];
#pragma unroll
    for (int mi = 0; mi < 2; mi++)
#pragma unroll
        for (int ni = 0; ni < 8; ni++)
#pragma unroll
            for (int r = 0; r < 4; r++) acc[mi][ni][r] = 0.f;

    {
        float4 a0 = *(const float4*)(Ag);
        float4 a1 = *(const float4*)(Ag + rstep);
        float4 w0 = *(const float4*)(Wg);
        float4 w1 = *(const float4*)(Wg + rstep);
        As[0][lrow     ][lcol+0]=to_tf32(a0.x); As[0][lrow     ][lcol+1]=to_tf32(a0.y);
        As[0][lrow     ][lcol+2]=to_tf32(a0.z); As[0][lrow     ][lcol+3]=to_tf32(a0.w);
        As[0][lrow + 64][lcol+0]=to_tf32(a1.x); As[0][lrow + 64][lcol+1]=to_tf32(a1.y);
        As[0][lrow + 64][lcol+2]=to_tf32(a1.z); As[0][lrow + 64][lcol+3]=to_tf32(a1.w);
        Ws[0][lrow     ][lcol+0]=to_tf32(w0.x); Ws[0][lrow     ][lcol+1]=to_tf32(w0.y);
        Ws[0][lrow     ][lcol+2]=to_tf32(w0.z); Ws[0][lrow     ][lcol+3]=to_tf32(w0.w);
        Ws[0][lrow + 64][lcol+0]=to_tf32(w1.x); Ws[0][lrow + 64][lcol+1]=to_tf32(w1.y);
        Ws[0][lrow + 64][lcol+2]=to_tf32(w1.z); Ws[0][lrow + 64][lcol+3]=to_tf32(w1.w);
    }
    __syncthreads();

    int buf = 0;
    for (int k0 = 0; k0 < K; k0 += 16) {
        float4 a0, a1, w0, w1;
        const bool has_next = (k0 + 16) < K;
        if (has_next) {
            a0 = *(const float4*)(Ag + k0 + 16);
            a1 = *(const float4*)(Ag + rstep + k0 + 16);
            w0 = *(const float4*)(Wg + k0 + 16);
            w1 = *(const float4*)(Wg + rstep + k0 + 16);
        }

#pragma unroll
        for (int ks = 0; ks < 16; ks += 8) {
            uint32_t af[2][4], bf[8][2];
#pragma unroll
            for (int mi = 0; mi < 2; mi++) {
                const int r = wm + mi * 16;
                af[mi][0] = __float_as_uint(As[buf][r + g    ][ks + t    ]);
                af[mi][1] = __float_as_uint(As[buf][r + g + 8][ks + t    ]);
                af[mi][2] = __float_as_uint(As[buf][r + g    ][ks + t + 4]);
                af[mi][3] = __float_as_uint(As[buf][r + g + 8][ks + t + 4]);
            }
#pragma unroll
            for (int ni = 0; ni < 8; ni++) {
                const int c = wn + ni * 8;
                bf[ni][0] = __float_as_uint(Ws[buf][c + g][ks + t    ]);
                bf[ni][1] = __float_as_uint(Ws[buf][c + g][ks + t + 4]);
            }
#pragma unroll
            for (int mi = 0; mi < 2; mi++)
#pragma unroll
                for (int ni = 0; ni < 8; ni++)
                    mma_tf32(acc[mi][ni], af[mi], bf[ni]);
        }

        if (has_next) {
            const int nb = buf ^ 1;
            As[nb][lrow     ][lcol+0]=to_tf32(a0.x); As[nb][lrow     ][lcol+1]=to_tf32(a0.y);
            As[nb][lrow     ][lcol+2]=to_tf32(a0.z); As[nb][lrow     ][lcol+3]=to_tf32(a0.w);
            As[nb][lrow + 64][lcol+0]=to_tf32(a1.x); As[nb][lrow + 64][lcol+1]=to_tf32(a1.y);
            As[nb][lrow + 64][lcol+2]=to_tf32(a1.z); As[nb][lrow + 64][lcol+3]=to_tf32(a1.w);
            Ws[nb][lrow     ][lcol+0]=to_tf32(w0.x); Ws[nb][lrow     ][lcol+1]=to_tf32(w0.y);
            Ws[nb][lrow     ][lcol+2]=to_tf32(w0.z); Ws[nb][lrow     ][lcol+3]=to_tf32(w0.w);
            Ws[nb][lrow + 64][lcol+0]=to_tf32(w1.x); Ws[nb][lrow + 64][lcol+1]=to_tf32(w1.y);
            Ws[nb][lrow + 64][lcol+2]=to_tf32(w1.z); Ws[nb][lrow + 64][lcol+3]=to_tf32(w1.w);
        }
        __syncthreads();
        buf ^= 1;
    }

#pragma unroll
    for (int mi = 0; mi < 2; mi++) {
#pragma unroll
        for (int ni = 0; ni < 8; ni++) {
            const int n = n0 + wn + ni * 8 + 2 * t;
            const float b0 = bias[n], b1 = bias[n + 1];
            const int mA = m0 + wm + mi * 16 + g;
            float2 v0; v0.x = acc[mi][ni][0] + b0; v0.y = acc[mi][ni][1] + b1;
            *(float2*)&C[(size_t)mA * N + n] = v0;
            float2 v1; v1.x = acc[mi][ni][2] + b0; v1.y = acc[mi][ni][3] + b1;
            *(float2*)&C[(size_t)(mA + 8) * N + n] = v1;
        }
    }
}

// ---------------------------------------------------------------------------
// Flash attention with tf32 mma.sync.
// Block = (128-query tile, b*h). 8 warps; warp w owns rows [w*16, w*16+16).
// Q fragments persistent in registers. K,V in smem natural [key][d] layout.
// P stays in registers: c-frag -> a-frag via 8 shuffles per k-chunk.
// ---------------------------------------------------------------------------
__global__ __launch_bounds__(256, 1) void attn_mma(const int* __restrict__ causal_p,
                                                   float* __restrict__ out)
{
    __shared__ float smem[8704];       // Qs[128][68] aliased with Ks[64][68]+Vs[64][68]
    float* Ks = smem;
    float* Vs = smem + 64 * 68;

    const int qtile = blockIdx.x;
    const int bh    = blockIdx.y;
    const int b     = bh >> 4;
    const int h     = bh & 15;
    const int tid   = threadIdx.x;
    const int w     = tid >> 5;
    const int lane  = tid & 31;
    const int g     = lane >> 2;
    const int t     = lane & 3;
    const int causal = *causal_p;

    const float sscale = 0.125f * 1.4426950408889634f;
    const float slope2 = (float)(exp2(-0.5 * (double)(h + 1)) * 1.4426950408889634);

    const float* qkv = g_qkv;
    const int q0 = qtile * 128;
    const int rg  = q0 + w * 16 + g;     // this thread's first row
    const int rg8 = rg + 8;              // second row

    // ---- Stage Q into smem (as tf32), then fragment into registers ----
    for (int it = 0; it < 8; it++) {
        const int i = it * 256 + tid;
        const int row = i >> 4;
        const int c4  = (i & 15) * 4;
        float4 v = *(const float4*)&qkv[(size_t)(b * SEQ + q0 + row) * TDIM + h * HD + c4];
        float* d = &smem[row * 68 + c4];
        d[0] = to_tf32(v.x); d[1] = to_tf32(v.y); d[2] = to_tf32(v.z); d[3] = to_tf32(v.w);
    }
    __syncthreads();

    uint32_t qa[8][4];
#pragma unroll
    for (int k = 0; k < 8; k++) {
        qa[k][0] = __float_as_uint(smem[(w * 16 + g    ) * 68 + k * 8 + t    ]);
        qa[k][1] = __float_as_uint(smem[(w * 16 + g + 8) * 68 + k * 8 + t    ]);
        qa[k][2] = __float_as_uint(smem[(w * 16 + g    ) * 68 + k * 8 + t + 4]);
        qa[k][3] = __float_as_uint(smem[(w * 16 + g + 8) * 68 + k * 8 + t + 4]);
    }

    float o[8][4];
#pragma unroll
    for (int ni = 0; ni < 8; ni++)
#pragma unroll
        for (int r = 0; r < 4; r++) o[ni][r] = 0.f;
    float m0 = -1e30f, m1 = -1e30f, l0 = 0.f, l1 = 0.f;

    const int ntiles = causal ? (2 * qtile + 2) : (SEQ / 64);

    for (int kt = 0; kt < ntiles; kt++) {
        __syncthreads();   // previous tile fully consumed (also: Q staging consumed)
        // Load K,V tile [64 keys][64 d], natural layout, tf32-rounded
        for (int it = 0; it < 4; it++) {
            const int i = it * 256 + tid;
            const int row = i >> 4;
            const int c4  = (i & 15) * 4;
            const size_t base = (size_t)(b * SEQ + kt * 64 + row) * TDIM + h * HD + c4;
            float4 kv = *(const float4*)&qkv[base + DIMM];
            float* dk = &Ks[row * 68 + c4];
            dk[0] = to_tf32(kv.x); dk[1] = to_tf32(kv.y); dk[2] = to_tf32(kv.z); dk[3] = to_tf32(kv.w);
            float4 vv = *(const float4*)&qkv[base + 2 * DIMM];
            float* dv = &Vs[row * 68 + c4];
            dv[0] = to_tf32(vv.x); dv[1] = to_tf32(vv.y); dv[2] = to_tf32(vv.z); dv[3] = to_tf32(vv.w);
        }
        __syncthreads();

        // Warp-level early-out: tile entirely above causal diagonal for all 16 rows
        if (causal && kt * 64 > q0 + w * 16 + 15) continue;

        // ---- S = Q K^T : c-frags sc[8][4] ----
        float sc[8][4];
#pragma unroll
        for (int ni = 0; ni < 8; ni++)
#pragma unroll
            for (int r = 0; r < 4; r++) sc[ni][r] = 0.f;

#pragma unroll
        for (int k = 0; k < 8; k++) {
            uint32_t kb[8][2];
#pragma unroll
            for (int ni = 0; ni < 8; ni++) {
                kb[ni][0] = __float_as_uint(Ks[(ni * 8 + g) * 68 + k * 8 + t    ]);
                kb[ni][1] = __float_as_uint(Ks[(ni * 8 + g) * 68 + k * 8 + t + 4]);
            }
#pragma unroll
            for (int ni = 0; ni < 8; ni++)
                mma_tf32(sc[ni], qa[k], kb[ni]);
        }

        // ---- Online softmax (log2 domain, ALiBi analytic) ----
        const bool need_mask = causal && (kt * 64 + 63 > rg);  // any col above row for either half? conservative per-thread
        float mx0 = -1e30f, mx1 = -1e30f;
#pragma unroll
        for (int ni = 0; ni < 8; ni++) {
#pragma unroll
            for (int e = 0; e < 2; e++) {
                const int col = kt * 64 + ni * 8 + 2 * t + e;
                float v0 = fmaf(sc[ni][e],     sscale, slope2 * (float)(col - rg));
                float v1 = fmaf(sc[ni][2 + e], sscale, slope2 * (float)(col - rg8));
                if (causal && col > rg)  v0 = -1e30f;
                if (causal && col > rg8) v1 = -1e30f;
                sc[ni][e]     = v0;
                sc[ni][2 + e] = v1;
                mx0 = fmaxf(mx0, v0);
                mx1 = fmaxf(mx1, v1);
            }
        }
        (void)need_mask;
        mx0 = fmaxf(mx0, __shfl_xor_sync(0xffffffffu, mx0, 1));
        mx0 = fmaxf(mx0, __shfl_xor_sync(0xffffffffu, mx0, 2));
        mx1 = fmaxf(mx1, __shfl_xor_sync(0xffffffffu, mx1, 1));
        mx1 = fmaxf(mx1, __shfl_xor_sync(0xffffffffu, mx1, 2));

        const float mn0 = fmaxf(m0, mx0);
        const float mn1 = fmaxf(m1, mx1);
        const float rs0 = exp2f(m0 - mn0);
        const float rs1 = exp2f(m1 - mn1);

        float sum0 = 0.f, sum1 = 0.f;
#pragma unroll
        for (int ni = 0; ni < 8; ni++) {
#pragma unroll
            for (int e = 0; e < 2; e++) {
                float p0 = exp2f(sc[ni][e]     - mn0);
                float p1 = exp2f(sc[ni][2 + e] - mn1);
                sum0 += p0; sum1 += p1;
                sc[ni][e]     = to_tf32(p0);
                sc[ni][2 + e] = to_tf32(p1);
            }
        }
        sum0 += __shfl_xor_sync(0xffffffffu, sum0, 1);
        sum0 += __shfl_xor_sync(0xffffffffu, sum0, 2);
        sum1 += __shfl_xor_sync(0xffffffffu, sum1, 1);
        sum1 += __shfl_xor_sync(0xffffffffu, sum1, 2);

        l0 = l0 * rs0 + sum0;
        l1 = l1 * rs1 + sum1;
        m0 = mn0; m1 = mn1;
#pragma unroll
        for (int ni = 0; ni < 8; ni++) {
            o[ni][0] *= rs0; o[ni][1] *= rs0;
            o[ni][2] *= rs1; o[ni][3] *= rs1;
        }

        // ---- O += P V : per k-chunk, permute P c-frag -> a-frag via shuffles ----
        const int src_lo = (lane & ~3) | (t >> 1);
        const int src_hi = src_lo + 2;
#pragma unroll
        for (int kc = 0; kc < 8; kc++) {
            float s0a = __shfl_sync(0xffffffffu, sc[kc][0], src_lo);
            float s0b = __shfl_sync(0xffffffffu, sc[kc][1], src_lo);
            float s2a = __shfl_sync(0xffffffffu, sc[kc][2], src_lo);
            float s2b = __shfl_sync(0xffffffffu, sc[kc][3], src_lo);
            float h0a = __shfl_sync(0xffffffffu, sc[kc][0], src_hi);
            float h0b = __shfl_sync(0xffffffffu, sc[kc][1], src_hi);
            float h2a = __shfl_sync(0xffffffffu, sc[kc][2], src_hi);
            float h2b = __shfl_sync(0xffffffffu, sc[kc][3], src_hi);
            uint32_t pa[4];
            pa[0] = __float_as_uint((t & 1) ? s0b : s0a);   // row g,   col kc*8+t
            pa[1] = __float_as_uint((t & 1) ? s2b : s2a);   // row g+8, col kc*8+t
            pa[2] = __float_as_uint((t & 1) ? h0b : h0a);   // row g,   col kc*8+t+4
            pa[3] = __float_as_uint((t & 1) ? h2b : h2a);   // row g+8, col kc*8+t+4

            uint32_t vb[8][2];
#pragma unroll
            for (int ni = 0; ni < 8; ni++) {
                vb[ni][0] = __float_as_uint(Vs[(kc * 8 + t    ) * 68 + ni * 8 + g]);
                vb[ni][1] = __float_as_uint(Vs[(kc * 8 + t + 4) * 68 + ni * 8 + g]);
            }
#pragma unroll
            for (int ni = 0; ni < 8; ni++)
                mma_tf32(o[ni], pa, vb[ni]);
        }
    }

    // ---- Epilogue ----
    const float inv0 = 1.f / l0;
    const float inv1 = 1.f / l1;
    const size_t row0 = (size_t)(b * SEQ + rg ) * DIMM + h * HD;
    const size_t row1 = (size_t)(b * SEQ + rg8) * DIMM + h * HD;
#pragma unroll
    for (int ni = 0; ni < 8; ni++) {
        const int n = ni * 8 + 2 * t;
        float2 v0; v0.x = o[ni][0] * inv0; v0.y = o[ni][1] * inv0;
        *(float2*)&out[row0 + n] = v0;
        float2 v1; v1.x = o[ni][2] * inv1; v1.y = o[ni][3] * inv1;
        *(float2*)&out[row1 + n] = v1;
    }
}

extern "C" void kernel_launch(void* const* d_in, const int* in_sizes, int n_in,
                              void* d_out, int out_size)
{
    const float* x      = (const float*)d_in[0];
    const int*   causal = (const int*)d_in[1];
    // d_in[2] = alibi_bias: unused (computed analytically in-kernel)
    const float* Wqkv   = (const float*)d_in[3];
    const float* bqkv   = (const float*)d_in[4];
    const float* Wout   = (const float*)d_in[5];
    const float* bout   = (const float*)d_in[6];
    float* out = (float*)d_out;

    float *qkv, *att;
    cudaGetSymbolAddress((void**)&qkv, g_qkv);
    cudaGetSymbolAddress((void**)&att, g_att);

    dim3 g1(TDIM / 128, BT / 128);
    tgemm_bias<<<g1, 256>>>(x, Wqkv, bqkv, qkv, TDIM, DIMM);

    dim3 g2(SEQ / 128, BATCH * HEADS);
    attn_mma<<<g2, 256>>>(causal, att);

    dim3 g3(DIMM / 128, BT / 128);
    tgemm_bias<<<g3, 256>>>(att, Wout, bout, out, DIMM, DIMM);
}

// round 7
// speedup vs baseline: 3.0884x; 1.0885x over previous
#include <cuda_runtime.h>
#include <math.h>
#include <stdint.h>

#define HEADS 16
#define HD    64
#define SEQ   2048
#define BATCH 2
#define DIMM  1024
#define TDIM  3072
#define BT    (BATCH*SEQ)

// Scratch (no cudaMalloc allowed)
__device__ float g_qkv[(size_t)BT * TDIM];     // [b*T][3*D], tf32-rounded values
__device__ float g_att[(size_t)BT * DIMM];     // [b*T][D],  tf32-rounded values
__device__ float g_w1[(size_t)TDIM * DIMM];    // rounded Wqkv
__device__ float g_w2[(size_t)DIMM * DIMM];    // rounded Wout

__device__ __forceinline__ float to_tf32(float x) {
    uint32_t u;
    asm("cvt.rna.tf32.f32 %0, %1;" : "=r"(u) : "f"(x));
    return __uint_as_float(u);
}

__device__ __forceinline__ void mma_tf32(float* c, const uint32_t* a, const uint32_t* b) {
    asm volatile(
        "mma.sync.aligned.m16n8k8.row.col.f32.tf32.tf32.f32 "
        "{%0,%1,%2,%3}, {%4,%5,%6,%7}, {%8,%9}, {%0,%1,%2,%3};\n"
        : "+f"(c[0]), "+f"(c[1]), "+f"(c[2]), "+f"(c[3])
        : "r"(a[0]), "r"(a[1]), "r"(a[2]), "r"(a[3]), "r"(b[0]), "r"(b[1]));
}

__device__ __forceinline__ void cp16(uint32_t s, const float* g) {
    asm volatile("cp.async.cg.shared.global [%0], [%1], 16;" :: "r"(s), "l"(g));
}
#define CP_COMMIT() asm volatile("cp.async.commit_group;")
#define CP_WAIT1()  asm volatile("cp.async.wait_group 1;")

// ---------------------------------------------------------------------------
// Prepass: tf32-round a weight matrix (float4 granularity).
// ---------------------------------------------------------------------------
__global__ void roundw_kernel(const float4* __restrict__ src, float4* __restrict__ dst, int n4)
{
    int i = blockIdx.x * 256 + threadIdx.x;
    if (i < n4) {
        float4 v = src[i];
        v.x = to_tf32(v.x); v.y = to_tf32(v.y); v.z = to_tf32(v.z); v.w = to_tf32(v.w);
        dst[i] = v;
    }
}

// ---------------------------------------------------------------------------
// C[M][N] = A[M][K] @ W[N][K]^T + bias[N] via tf32 mma, cp.async 3-stage pipe.
// BM=BN=128, BK=16, 256 threads, warp tile 32x64. Row stride 28 floats
// (112B: 16B-aligned for cp.async; g*28%32 distinct -> conflict-free frags).
// CVT_A: round A fragments in-loop (A not pre-rounded). ROUND_OUT: round output.
// ---------------------------------------------------------------------------
template<bool CVT_A, bool ROUND_OUT>
__global__ __launch_bounds__(256, 2) void tgemm_cp(
    const float* __restrict__ A, const float* __restrict__ W,
    const float* __restrict__ bias, float* __restrict__ C,
    int N, int K)
{
    extern __shared__ float sm[];
    float* As = sm;                    // [3][128][28]
    float* Ws = sm + 3 * 128 * 28;     // [3][128][28]

    const int tid  = threadIdx.x;
    const int warp = tid >> 5;
    const int lane = tid & 31;
    const int g    = lane >> 2;
    const int t    = lane & 3;

    const int m0 = blockIdx.y * 128;
    const int n0 = blockIdx.x * 128;
    const int wm = (warp >> 1) * 32;
    const int wn = (warp & 1) * 64;

    const int lrow = tid >> 2;         // 0..63
    const int lcol = (tid & 3) * 4;    // 0,4,8,12

    const float* Ag = A + (size_t)(m0 + lrow) * K + lcol;
    const float* Wg = W + (size_t)(n0 + lrow) * K + lcol;
    const size_t rs = (size_t)64 * K;

    const uint32_t stg  = 128 * 28 * 4;
    const uint32_t half = 64 * 28 * 4;
    const uint32_t sa = (uint32_t)__cvta_generic_to_shared(As) + (uint32_t)(lrow * 28 + lcol) * 4;
    const uint32_t sw = (uint32_t)__cvta_generic_to_shared(Ws) + (uint32_t)(lrow * 28 + lcol) * 4;

    float acc[2][8][4];
#pragma unroll
    for (int mi = 0; mi < 2; mi++)
#pragma unroll
        for (int ni = 0; ni < 8; ni++)
#pragma unroll
            for (int r = 0; r < 4; r++) acc[mi][ni][r] = 0.f;

    // Prologue: stages 0 and 1 in flight
#pragma unroll
    for (int s = 0; s < 2; s++) {
        cp16(sa + s * stg,        Ag + s * 16);
        cp16(sa + s * stg + half, Ag + rs + s * 16);
        cp16(sw + s * stg,        Wg + s * 16);
        cp16(sw + s * stg + half, Wg + rs + s * 16);
        CP_COMMIT();
    }

    const int niter = K / 16;
    int buf = 0;
    for (int it = 0; it < niter; it++) {
        CP_WAIT1();
        __syncthreads();

        if (it + 2 < niter) {
            int s = buf + 2; if (s >= 3) s -= 3;
            const int ko = (it + 2) * 16;
            cp16(sa + s * stg,        Ag + ko);
            cp16(sa + s * stg + half, Ag + rs + ko);
            cp16(sw + s * stg,        Wg + ko);
            cp16(sw + s * stg + half, Wg + rs + ko);
        }
        CP_COMMIT();

        const float* Ab = As + buf * 128 * 28;
        const float* Wb = Ws + buf * 128 * 28;
#pragma unroll
        for (int ks = 0; ks < 16; ks += 8) {
            uint32_t af[2][4], bf[8][2];
#pragma unroll
            for (int mi = 0; mi < 2; mi++) {
                const int r = wm + mi * 16;
                float a0 = Ab[(r + g    ) * 28 + ks + t    ];
                float a1 = Ab[(r + g + 8) * 28 + ks + t    ];
                float a2 = Ab[(r + g    ) * 28 + ks + t + 4];
                float a3 = Ab[(r + g + 8) * 28 + ks + t + 4];
                if (CVT_A) { a0 = to_tf32(a0); a1 = to_tf32(a1); a2 = to_tf32(a2); a3 = to_tf32(a3); }
                af[mi][0] = __float_as_uint(a0); af[mi][1] = __float_as_uint(a1);
                af[mi][2] = __float_as_uint(a2); af[mi][3] = __float_as_uint(a3);
            }
#pragma unroll
            for (int ni = 0; ni < 8; ni++) {
                const int c = wn + ni * 8;
                bf[ni][0] = __float_as_uint(Wb[(c + g) * 28 + ks + t    ]);
                bf[ni][1] = __float_as_uint(Wb[(c + g) * 28 + ks + t + 4]);
            }
#pragma unroll
            for (int mi = 0; mi < 2; mi++)
#pragma unroll
                for (int ni = 0; ni < 8; ni++)
                    mma_tf32(acc[mi][ni], af[mi], bf[ni]);
        }
        buf++; if (buf == 3) buf = 0;
    }

#pragma unroll
    for (int mi = 0; mi < 2; mi++) {
#pragma unroll
        for (int ni = 0; ni < 8; ni++) {
            const int n = n0 + wn + ni * 8 + 2 * t;
            const float b0 = bias[n], b1 = bias[n + 1];
            const int mA = m0 + wm + mi * 16 + g;
            float2 v0, v1;
            if (ROUND_OUT) {
                v0.x = to_tf32(acc[mi][ni][0] + b0); v0.y = to_tf32(acc[mi][ni][1] + b1);
                v1.x = to_tf32(acc[mi][ni][2] + b0); v1.y = to_tf32(acc[mi][ni][3] + b1);
            } else {
                v0.x = acc[mi][ni][0] + b0; v0.y = acc[mi][ni][1] + b1;
                v1.x = acc[mi][ni][2] + b0; v1.y = acc[mi][ni][3] + b1;
            }
            *(float2*)&C[(size_t)mA * N + n] = v0;
            *(float2*)&C[(size_t)(mA + 8) * N + n] = v1;
        }
    }
}

// ---------------------------------------------------------------------------
// Flash attention, tf32 mma, cp.async double-buffered K/V.
// Block = (128-query tile, b*h). Warp w owns rows [w*16, w*16+16).
// g_qkv is pre-rounded by GEMM1's epilogue -> no cvt on staging.
// Stage s at sm + s*8704 floats: Ks [64][68] then Vs [64][68].
// ---------------------------------------------------------------------------
__global__ __launch_bounds__(256, 1) void attn_mma(const int* __restrict__ causal_p,
                                                   float* __restrict__ out)
{
    extern __shared__ float sm[];

    const int qtile = blockIdx.x;
    const int bh    = blockIdx.y;
    const int b     = bh >> 4;
    const int h     = bh & 15;
    const int tid   = threadIdx.x;
    const int w     = tid >> 5;
    const int lane  = tid & 31;
    const int g     = lane >> 2;
    const int t     = lane & 3;
    const int causal = *causal_p;

    const float sscale = 0.125f * 1.4426950408889634f;
    const float slope2 = (float)(exp2(-0.5 * (double)(h + 1)) * 1.4426950408889634);

    const float* qkv = g_qkv;
    const int q0 = qtile * 128;
    const int rg  = q0 + w * 16 + g;
    const int rg8 = rg + 8;

    const uint32_t smu = (uint32_t)__cvta_generic_to_shared(sm);

    // Issue KV tile 0 into stage 0
    {
#pragma unroll
        for (int itr = 0; itr < 4; itr++) {
            const int i = itr * 256 + tid;
            const int row = i >> 4;
            const int c4  = (i & 15) * 4;
            const float* gk = qkv + (size_t)(b * SEQ + row) * TDIM + h * HD + DIMM + c4;
            const uint32_t dk = smu + (uint32_t)(row * 68 + c4) * 4;
            cp16(dk, gk);
            cp16(dk + 4352 * 4, gk + DIMM);
        }
        CP_COMMIT();
    }

    // Stage Q (plain loads, already rounded) into stage-1 region, extract frags
    float* Qs = sm + 8704;
    for (int itr = 0; itr < 8; itr++) {
        const int i = itr * 256 + tid;
        const int row = i >> 4;
        const int c4  = (i & 15) * 4;
        *(float4*)&Qs[row * 68 + c4] =
            *(const float4*)&qkv[(size_t)(b * SEQ + q0 + row) * TDIM + h * HD + c4];
    }
    __syncthreads();

    uint32_t qa[8][4];
#pragma unroll
    for (int k = 0; k < 8; k++) {
        qa[k][0] = __float_as_uint(Qs[(w * 16 + g    ) * 68 + k * 8 + t    ]);
        qa[k][1] = __float_as_uint(Qs[(w * 16 + g + 8) * 68 + k * 8 + t    ]);
        qa[k][2] = __float_as_uint(Qs[(w * 16 + g    ) * 68 + k * 8 + t + 4]);
        qa[k][3] = __float_as_uint(Qs[(w * 16 + g + 8) * 68 + k * 8 + t + 4]);
    }
    __syncthreads();

    const int ntiles = causal ? (2 * qtile + 2) : (SEQ / 64);

    // Issue KV tile 1 into stage 1 (overwrites Q staging — safe after sync)
    if (ntiles > 1) {
#pragma unroll
        for (int itr = 0; itr < 4; itr++) {
            const int i = itr * 256 + tid;
            const int row = i >> 4;
            const int c4  = (i & 15) * 4;
            const float* gk = qkv + (size_t)(b * SEQ + 64 + row) * TDIM + h * HD + DIMM + c4;
            const uint32_t dk = smu + (uint32_t)(8704 + row * 68 + c4) * 4;
            cp16(dk, gk);
            cp16(dk + 4352 * 4, gk + DIMM);
        }
    }
    CP_COMMIT();

    float o[8][4];
#pragma unroll
    for (int ni = 0; ni < 8; ni++)
#pragma unroll
        for (int r = 0; r < 4; r++) o[ni][r] = 0.f;
    float m0 = -1e30f, m1 = -1e30f, l0 = 0.f, l1 = 0.f;

    for (int kt = 0; kt < ntiles; kt++) {
        CP_WAIT1();
        __syncthreads();

        const float* Ks = sm + (kt & 1) * 8704;
        const float* Vs = Ks + 4352;

        const bool active = !(causal && kt * 64 > q0 + w * 16 + 15);
        if (active) {
            // ---- S = Q K^T ----
            float sc[8][4];
#pragma unroll
            for (int ni = 0; ni < 8; ni++)
#pragma unroll
                for (int r = 0; r < 4; r++) sc[ni][r] = 0.f;

#pragma unroll
            for (int k = 0; k < 8; k++) {
                uint32_t kb[8][2];
#pragma unroll
                for (int ni = 0; ni < 8; ni++) {
                    kb[ni][0] = __float_as_uint(Ks[(ni * 8 + g) * 68 + k * 8 + t    ]);
                    kb[ni][1] = __float_as_uint(Ks[(ni * 8 + g) * 68 + k * 8 + t + 4]);
                }
#pragma unroll
                for (int ni = 0; ni < 8; ni++)
                    mma_tf32(sc[ni], qa[k], kb[ni]);
            }

            // ---- Online softmax (log2 domain, ALiBi analytic) ----
            float mx0 = -1e30f, mx1 = -1e30f;
#pragma unroll
            for (int ni = 0; ni < 8; ni++) {
#pragma unroll
                for (int e = 0; e < 2; e++) {
                    const int col = kt * 64 + ni * 8 + 2 * t + e;
                    float v0 = fmaf(sc[ni][e],     sscale, slope2 * (float)(col - rg));
                    float v1 = fmaf(sc[ni][2 + e], sscale, slope2 * (float)(col - rg8));
                    if (causal && col > rg)  v0 = -1e30f;
                    if (causal && col > rg8) v1 = -1e30f;
                    sc[ni][e]     = v0;
                    sc[ni][2 + e] = v1;
                    mx0 = fmaxf(mx0, v0);
                    mx1 = fmaxf(mx1, v1);
                }
            }
            mx0 = fmaxf(mx0, __shfl_xor_sync(0xffffffffu, mx0, 1));
            mx0 = fmaxf(mx0, __shfl_xor_sync(0xffffffffu, mx0, 2));
            mx1 = fmaxf(mx1, __shfl_xor_sync(0xffffffffu, mx1, 1));
            mx1 = fmaxf(mx1, __shfl_xor_sync(0xffffffffu, mx1, 2));

            const float mn0 = fmaxf(m0, mx0);
            const float mn1 = fmaxf(m1, mx1);
            const float rs0 = exp2f(m0 - mn0);
            const float rs1 = exp2f(m1 - mn1);

            float sum0 = 0.f, sum1 = 0.f;
#pragma unroll
            for (int ni = 0; ni < 8; ni++) {
#pragma unroll
                for (int e = 0; e < 2; e++) {
                    float p0 = exp2f(sc[ni][e]     - mn0);
                    float p1 = exp2f(sc[ni][2 + e] - mn1);
                    sum0 += p0; sum1 += p1;
                    sc[ni][e]     = to_tf32(p0);
                    sc[ni][2 + e] = to_tf32(p1);
                }
            }
            sum0 += __shfl_xor_sync(0xffffffffu, sum0, 1);
            sum0 += __shfl_xor_sync(0xffffffffu, sum0, 2);
            sum1 += __shfl_xor_sync(0xffffffffu, sum1, 1);
            sum1 += __shfl_xor_sync(0xffffffffu, sum1, 2);

            l0 = l0 * rs0 + sum0;
            l1 = l1 * rs1 + sum1;
            m0 = mn0; m1 = mn1;
#pragma unroll
            for (int ni = 0; ni < 8; ni++) {
                o[ni][0] *= rs0; o[ni][1] *= rs0;
                o[ni][2] *= rs1; o[ni][3] *= rs1;
            }

            // ---- O += P V : permute P c-frag -> a-frag via shuffles ----
            const int src_lo = (lane & ~3) | (t >> 1);
            const int src_hi = src_lo + 2;
#pragma unroll
            for (int kc = 0; kc < 8; kc++) {
                float s0a = __shfl_sync(0xffffffffu, sc[kc][0], src_lo);
                float s0b = __shfl_sync(0xffffffffu, sc[kc][1], src_lo);
                float s2a = __shfl_sync(0xffffffffu, sc[kc][2], src_lo);
                float s2b = __shfl_sync(0xffffffffu, sc[kc][3], src_lo);
                float h0a = __shfl_sync(0xffffffffu, sc[kc][0], src_hi);
                float h0b = __shfl_sync(0xffffffffu, sc[kc][1], src_hi);
                float h2a = __shfl_sync(0xffffffffu, sc[kc][2], src_hi);
                float h2b = __shfl_sync(0xffffffffu, sc[kc][3], src_hi);
                uint32_t pa[4];
                pa[0] = __float_as_uint((t & 1) ? s0b : s0a);
                pa[1] = __float_as_uint((t & 1) ? s2b : s2a);
                pa[2] = __float_as_uint((t & 1) ? h0b : h0a);
                pa[3] = __float_as_uint((t & 1) ? h2b : h2a);

                uint32_t vb[8][2];
#pragma unroll
                for (int ni = 0; ni < 8; ni++) {
                    vb[ni][0] = __float_as_uint(Vs[(kc * 8 + t    ) * 68 + ni * 8 + g]);
                    vb[ni][1] = __float_as_uint(Vs[(kc * 8 + t + 4) * 68 + ni * 8 + g]);
                }
#pragma unroll
                for (int ni = 0; ni < 8; ni++)
                    mma_tf32(o[ni], pa, vb[ni]);
            }
        }
        __syncthreads();

        // Prefetch tile kt+2 into stage (kt&1) — all warps done with it
        if (kt + 2 < ntiles) {
#pragma unroll
            for (int itr = 0; itr < 4; itr++) {
                const int i = itr * 256 + tid;
                const int row = i >> 4;
                const int c4  = (i & 15) * 4;
                const float* gk = qkv + (size_t)(b * SEQ + (kt + 2) * 64 + row) * TDIM + h * HD + DIMM + c4;
                const uint32_t dk = smu + (uint32_t)((kt & 1) * 8704 + row * 68 + c4) * 4;
                cp16(dk, gk);
                cp16(dk + 4352 * 4, gk + DIMM);
            }
        }
        CP_COMMIT();
    }

    // ---- Epilogue (rounded for GEMM3's cvt-free consumption) ----
    const float inv0 = 1.f / l0;
    const float inv1 = 1.f / l1;
    const size_t row0 = (size_t)(b * SEQ + rg ) * DIMM + h * HD;
    const size_t row1 = (size_t)(b * SEQ + rg8) * DIMM + h * HD;
#pragma unroll
    for (int ni = 0; ni < 8; ni++) {
        const int n = ni * 8 + 2 * t;
        float2 v0; v0.x = to_tf32(o[ni][0] * inv0); v0.y = to_tf32(o[ni][1] * inv0);
        *(float2*)&out[row0 + n] = v0;
        float2 v1; v1.x = to_tf32(o[ni][2] * inv1); v1.y = to_tf32(o[ni][3] * inv1);
        *(float2*)&out[row1 + n] = v1;
    }
}

extern "C" void kernel_launch(void* const* d_in, const int* in_sizes, int n_in,
                              void* d_out, int out_size)
{
    const float* x      = (const float*)d_in[0];
    const int*   causal = (const int*)d_in[1];
    // d_in[2] = alibi_bias: unused (computed analytically in-kernel)
    const float* Wqkv   = (const float*)d_in[3];
    const float* bqkv   = (const float*)d_in[4];
    const float* Wout   = (const float*)d_in[5];
    const float* bout   = (const float*)d_in[6];
    float* out = (float*)d_out;

    float *qkv, *att, *w1, *w2;
    cudaGetSymbolAddress((void**)&qkv, g_qkv);
    cudaGetSymbolAddress((void**)&att, g_att);
    cudaGetSymbolAddress((void**)&w1, g_w1);
    cudaGetSymbolAddress((void**)&w2, g_w2);

    const int gemm_smem = 2 * 3 * 128 * 28 * 4;  // 86016 B
    const int attn_smem = 2 * 2 * 64 * 68 * 4;   // 69632 B
    static bool attr_set = false;
    if (!attr_set) {
        cudaFuncSetAttribute(tgemm_cp<true, true>,   cudaFuncAttributeMaxDynamicSharedMemorySize, gemm_smem);
        cudaFuncSetAttribute(tgemm_cp<false, false>, cudaFuncAttributeMaxDynamicSharedMemorySize, gemm_smem);
        cudaFuncSetAttribute(attn_mma, cudaFuncAttributeMaxDynamicSharedMemorySize, attn_smem);
        attr_set = true;
    }

    // Prepass: round weights once per launch
    roundw_kernel<<<(TDIM * DIMM / 4 + 255) / 256, 256>>>((const float4*)Wqkv, (float4*)w1, TDIM * DIMM / 4);
    roundw_kernel<<<(DIMM * DIMM / 4 + 255) / 256, 256>>>((const float4*)Wout, (float4*)w2, DIMM * DIMM / 4);

    dim3 g1(TDIM / 128, BT / 128);
    tgemm_cp<true, true><<<g1, 256, gemm_smem>>>(x, w1, bqkv, qkv, TDIM, DIMM);

    dim3 g2(SEQ / 128, BATCH * HEADS);
    attn_mma<<<g2, 256, attn_smem>>>(causal, att);

    dim3 g3(DIMM / 128, BT / 128);
    tgemm_cp<false, false><<<g3, 256, gemm_smem>>>(att, w2, bout, out, DIMM, DIMM);
}